// round 14
// baseline (speedup 1.0000x reference)
#include <cuda_runtime.h>

#define N_SPH 128
#define CAP   256
#define TPB   256
#define PPT   1024          // points per tile
typedef unsigned long long u64;

#define FASTVAL 0.4317347049363836f   // -ln(1e-6)/32

// ---- packed f32x2 helpers (sm_100+) ----
__device__ __forceinline__ u64 pk2(float lo, float hi) {
    u64 r; asm("mov.b64 %0, {%1, %2};" : "=l"(r) : "f"(lo), "f"(hi)); return r;
}
__device__ __forceinline__ float2 up2(u64 v) {
    float2 f; asm("mov.b64 {%0, %1}, %2;" : "=f"(f.x), "=f"(f.y) : "l"(v)); return f;
}
__device__ __forceinline__ u64 f2fma(u64 a, u64 b, u64 c) {
    u64 d; asm("fma.rn.f32x2 %0, %1, %2, %3;" : "=l"(d) : "l"(a), "l"(b), "l"(c)); return d;
}
__device__ __forceinline__ u64 f2mul(u64 a, u64 b) {
    u64 d; asm("mul.rn.f32x2 %0, %1, %2;" : "=l"(d) : "l"(a), "l"(b)); return d;
}
__device__ __forceinline__ u64 f2add(u64 a, u64 b) {
    u64 d; asm("add.rn.f32x2 %0, %1, %2;" : "=l"(d) : "l"(a), "l"(b)); return d;
}
__device__ __forceinline__ float sqrt_ap(float x) {
    float r; asm("sqrt.approx.f32 %0, %1;" : "=f"(r) : "f"(x)); return r;
}
__device__ __forceinline__ float ex2_ap(float x) {
    float r; asm("ex2.approx.f32 %0, %1;" : "=f"(r) : "f"(x)); return r;
}
__device__ __forceinline__ float lg2_ap(float x) {
    float r; asm("lg2.approx.f32 %0, %1;" : "=f"(r) : "f"(x)); return r;
}

// classify 4 points, write FASTVAL for far ones, compact near ones into sbuf
__device__ __forceinline__ void classify_compact(
    int base, float4 va, float4 vb, float4 vc, bool inb, float R2,
    const float* __restrict__ shc, float4* sbuf, int* s_cnt_t,
    float* __restrict__ out, int tid) {

    float x[4], y[4], z[4];
    bool nearf[4] = {false, false, false, false};
    int cnt = 0;
    if (inb) {
        x[0] = va.x; y[0] = va.y; z[0] = va.z;
        x[1] = va.w; y[1] = vb.x; z[1] = vb.y;
        x[2] = vb.z; y[2] = vb.w; z[2] = vc.x;
        x[3] = vc.y; y[3] = vc.z; z[3] = vc.w;
        #pragma unroll
        for (int k = 0; k < 4; ++k) {
            float n2 = fmaf(x[k], x[k], fmaf(y[k], y[k], z[k] * z[k]));
            nearf[k] = n2 < R2;
            if (!nearf[k]) out[base + k] = FASTVAL;
            cnt += nearf[k] ? 1 : 0;
        }
    }
    unsigned mask = 0xffffffffu;
    int lane = tid & 31;
    int incl = cnt;
    #pragma unroll
    for (int d = 1; d < 32; d <<= 1) {
        int v = __shfl_up_sync(mask, incl, d);
        if (lane >= d) incl += v;
    }
    int total = __shfl_sync(mask, incl, 31);
    int wbase = 0;
    if (lane == 0) wbase = (total > 0) ? atomicAdd(s_cnt_t, total) : 0;
    wbase = __shfl_sync(mask, wbase, 0);
    int off = wbase + incl - cnt;
    #pragma unroll
    for (int k = 0; k < 4; ++k) {
        if (nearf[k]) {
            if (off < CAP) {
                sbuf[off] = make_float4(x[k], y[k], z[k], __int_as_float(base + k));
            } else {
                // overflow slow path: full scalar loop (correct, rare)
                float ssum = 0.f;
                for (int i = 0; i < N_SPH; ++i) {
                    const float* s = shc + i * 28;
                    float qx = fmaf(s[0], x[k], fmaf(s[2],  y[k], fmaf(s[4],  z[k], s[6])));
                    float qy = fmaf(s[8], x[k], fmaf(s[10], y[k], fmaf(s[12], z[k], s[14])));
                    float qz = fmaf(s[16], x[k], fmaf(s[18], y[k], fmaf(s[20], z[k], s[22])));
                    float d2 = fmaf(qx, qx, fmaf(qy, qy, qz * qz));
                    ssum += ex2_ap(fmaf(sqrt_ap(d2), -46.16624130844683f, s[24]));
                }
                out[base + k] = lg2_ap(fmaxf(ssum, 1e-6f)) * -0.021660849392498290f;
            }
            off++;
        }
    }
}

// phase C + D on the compacted tile (call after __syncthreads)
__device__ __forceinline__ void compute_finalize(
    int count, int ident,
    const float* __restrict__ shc, const float* __restrict__ shc2,
    const float4* sbuf, float* spart, float* __restrict__ out, int tid) {

    int pairs = (count + 1) >> 1;
    int total_u = ((pairs + 31) >> 5) << 7;   // pairs rounded to 32, x4 groups

    for (int u = tid; u < total_u; u += TPB) {
        int j = ((u >> 7) << 5) | (u & 31);
        int g = (u >> 5) & 3;                 // warp-uniform group
        if (j >= pairs) continue;

        int ia = 2 * j;
        int ib = min(2 * j + 1, count - 1);
        float4 A = sbuf[ia];
        float4 B = sbuf[ib];

        u64 X = pk2(A.x, B.x), Y = pk2(A.y, B.y), Z = pk2(A.z, B.z);
        float s0 = 0.f, s1 = 0.f;

        if (ident) {
            const float* cb2 = shc2 + g * (32 * 8);
            #pragma unroll 4
            for (int sp = 0; sp < 32; ++sp) {
                const ulonglong2* C = reinterpret_cast<const ulonglong2*>(cb2 + sp * 8);
                ulonglong2 n0 = C[0];  // (ncx, ncy)
                ulonglong2 n1 = C[1];  // (ncz, b)
                u64 qx = f2add(X, n0.x);
                u64 qy = f2add(Y, n0.y);
                u64 qz = f2add(Z, n1.x);
                u64 d2 = f2fma(qx, qx, f2fma(qy, qy, f2mul(qz, qz)));
                float2 d  = up2(d2);
                float2 bs = up2(n1.y);
                s0 += ex2_ap(fmaf(sqrt_ap(d.x), -46.16624130844683f, bs.x));
                s1 += ex2_ap(fmaf(sqrt_ap(d.y), -46.16624130844683f, bs.y));
            }
        } else {
            const float* cb = shc + g * (32 * 28);
            #pragma unroll 4
            for (int sp = 0; sp < 32; ++sp) {
                const ulonglong2* C = reinterpret_cast<const ulonglong2*>(cb + sp * 28);
                ulonglong2 m0 = C[0], m1 = C[1], m2 = C[2];
                ulonglong2 m3 = C[3], m4 = C[4], m5 = C[5];
                u64 bb = reinterpret_cast<const u64*>(C)[12];
                u64 qx = f2fma(m0.x, X, f2fma(m0.y, Y, f2fma(m1.x, Z, m1.y)));
                u64 qy = f2fma(m2.x, X, f2fma(m2.y, Y, f2fma(m3.x, Z, m3.y)));
                u64 qz = f2fma(m4.x, X, f2fma(m4.y, Y, f2fma(m5.x, Z, m5.y)));
                u64 d2 = f2fma(qx, qx, f2fma(qy, qy, f2mul(qz, qz)));
                float2 d  = up2(d2);
                float2 bs = up2(bb);
                s0 += ex2_ap(fmaf(sqrt_ap(d.x), -46.16624130844683f, bs.x));
                s1 += ex2_ap(fmaf(sqrt_ap(d.y), -46.16624130844683f, bs.y));
            }
        }

        spart[g * 257 + ia] = s0;
        if (2 * j + 1 < count) spart[g * 257 + ib] = s1;
    }
    __syncthreads();

    const float NEG_LN2_32 = -0.021660849392498290f;
    for (int pt = tid; pt < count; pt += TPB) {
        float a0 = spart[pt];
        float a1 = spart[257 + pt];
        float a2 = spart[2 * 257 + pt];
        float a3 = spart[3 * 257 + pt];
        float s = (a0 + a1) + (a2 + a3);
        out[__float_as_int(sbuf[pt].w)] = lg2_ap(fmaxf(s, 1e-6f)) * NEG_LN2_32;
    }
}

__global__ void __launch_bounds__(TPB, 4) smoothed_fused(
    const float* __restrict__ p,
    const float* __restrict__ centers,
    const float* __restrict__ radii,
    const float* __restrict__ tfs,
    float* __restrict__ out, int npts) {

    __shared__ __align__(16) float  shc[N_SPH * 28];   // general consts
    __shared__ __align__(16) float  shc2[N_SPH * 8];   // identity consts
    __shared__ __align__(16) float4 sbuf[CAP];
    __shared__ float  spart[4 * 257];
    __shared__ float  s_red[8];
    __shared__ float  s_R2;
    __shared__ int    s_cnt[2];
    __shared__ int    s_ident;

    const int tid = threadIdx.x;
    if (tid == 0) { s_cnt[0] = 0; s_cnt[1] = 0; s_ident = 1; }

    // ---- tile 0 point loads ----
    int base0 = blockIdx.x * (2 * PPT) + tid * 4;
    long f0 = (long)blockIdx.x * (2 * PPT * 3 / 4) + tid * 3;
    const float4* p4 = reinterpret_cast<const float4*>(p);
    float4 va, vb, vc;
    bool inb0 = base0 + 3 < npts;
    if (inb0) { va = p4[f0]; vb = p4[f0 + 1]; vc = p4[f0 + 2]; }
    __syncthreads();   // counter init visible

    // ---- phase A (once per block): consts + LSE threshold ----
    float my_sum = 0.0f, my_sig = 1e30f;
    if (tid < N_SPH) {
        int i = tid;
        float T[3][3];
        bool identl = true;
        #pragma unroll
        for (int r = 0; r < 3; ++r)
            #pragma unroll
            for (int c = 0; c < 3; ++c) {
                float tv = tfs[i * 9 + r * 3 + c];
                if (tv != 0.0f) identl = false;
                T[r][c] = tv + ((r == c) ? 1.0f : 0.0f);
            }
        if (!identl) atomicAnd(&s_ident, 0);

        float cx = centers[i * 3], cy = centers[i * 3 + 1], cz = centers[i * 3 + 2];
        float rad = radii[i];
        float b = 46.16624130844683f * rad;  // 32*log2(e)*r

        float* s = shc + i * 28;
        #pragma unroll
        for (int r = 0; r < 3; ++r) {
            float cs3[4] = {T[r][0], T[r][1], T[r][2],
                            (r == 0 ? -cx : (r == 1 ? -cy : -cz))};
            #pragma unroll
            for (int c = 0; c < 4; ++c) {
                s[(r * 4 + c) * 2]     = cs3[c];
                s[(r * 4 + c) * 2 + 1] = cs3[c];
            }
        }
        s[24] = b; s[25] = b; s[26] = 0.f; s[27] = 0.f;

        float* s2 = shc2 + i * 8;
        s2[0] = -cx; s2[1] = -cx;
        s2[2] = -cy; s2[3] = -cy;
        s2[4] = -cz; s2[5] = -cz;
        s2[6] = b;   s2[7] = b;

        float M00 = 0, M11 = 0, M22 = 0, M01 = 0, M02 = 0, M12 = 0;
        #pragma unroll
        for (int k = 0; k < 3; ++k) {
            float t0 = T[k][0], t1 = T[k][1], t2 = T[k][2];
            M00 = fmaf(t0, t0, M00); M11 = fmaf(t1, t1, M11); M22 = fmaf(t2, t2, M22);
            M01 = fmaf(t0, t1, M01); M02 = fmaf(t0, t2, M02); M12 = fmaf(t1, t2, M12);
        }
        float q  = (M00 + M11 + M22) * (1.0f / 3.0f);
        float a0 = M00 - q, a1 = M11 - q, a2 = M22 - q;
        float p2 = a0 * a0 + a1 * a1 + a2 * a2
                 + 2.0f * (M01 * M01 + M02 * M02 + M12 * M12);
        float lmin = q - 2.001f * sqrtf(fmaxf(p2, 0.0f) * (1.0f / 6.0f)) - 1e-6f;
        my_sig = sqrtf(fmaxf(lmin, 0.0f)) * 0.999f;

        float cn = sqrtf(cx * cx + cy * cy + cz * cz) * 1.0002f + 1e-7f;
        my_sum = expf(32.0f * (cn + rad));
    }
    #pragma unroll
    for (int d = 16; d; d >>= 1) {
        my_sum += __shfl_xor_sync(0xffffffffu, my_sum, d);
        my_sig  = fminf(my_sig, __shfl_xor_sync(0xffffffffu, my_sig, d));
    }
    if ((tid & 31) == 0 && tid < N_SPH) {
        s_red[tid >> 5]       = my_sum;
        s_red[(tid >> 5) + 4] = my_sig;
    }
    __syncthreads();
    if (tid == 0) {
        float S    = ((s_red[0] + s_red[1]) + (s_red[2] + s_red[3])) * 1.01f;
        float sigg = fminf(fminf(s_red[4], s_red[5]), fminf(s_red[6], s_red[7]));
        float thr2 = 1e30f;
        if (sigg > 1e-6f && !(S != S)) {
            float Rnum = logf(S) + 13.8155106f + 0.03f;
            if (Rnum <= 0.0f)       thr2 = 0.0f;
            else if (Rnum < 1e15f)  { float R = Rnum / (32.0f * sigg); thr2 = R * R * 1.002f; }
        }
        s_R2 = thr2;
    }
    __syncthreads();
    float R2 = s_R2;
    int ident = s_ident;

    // ================== TILE 0 ==================
    classify_compact(base0, va, vb, vc, inb0, R2, shc, sbuf, &s_cnt[0], out, tid);

    // prefetch tile 1 points (in flight during tile 0 compute)
    int base1 = base0 + PPT;
    long f1 = f0 + (PPT * 3 / 4);
    float4 wa, wb, wc;
    bool inb1 = base1 + 3 < npts;
    if (inb1) { wa = p4[f1]; wb = p4[f1 + 1]; wc = p4[f1 + 2]; }

    __syncthreads();
    int count0 = min(s_cnt[0], CAP);
    compute_finalize(count0, ident, shc, shc2, sbuf, spart, out, tid);
    __syncthreads();   // sbuf/spart reuse safe

    // ================== TILE 1 ==================
    classify_compact(base1, wa, wb, wc, inb1, R2, shc, sbuf, &s_cnt[1], out, tid);
    __syncthreads();
    int count1 = min(s_cnt[1], CAP);
    compute_finalize(count1, ident, shc, shc2, sbuf, spart, out, tid);
}

extern "C" void kernel_launch(void* const* d_in, const int* in_sizes, int n_in,
                              void* d_out, int out_size) {
    const float* p       = (const float*)d_in[0];
    const float* centers = (const float*)d_in[1];
    const float* radii   = (const float*)d_in[2];
    const float* tfs     = (const float*)d_in[3];
    float* out = (float*)d_out;

    int npts = in_sizes[0] / 3;
    int blocks = (npts + 2 * PPT - 1) / (2 * PPT);   // 512 blocks for 1M pts
    smoothed_fused<<<blocks, TPB>>>(p, centers, radii, tfs, out, npts);
}

// round 15
// speedup vs baseline: 1.0111x; 1.0111x over previous
#include <cuda_runtime.h>

#define N_SPH 128
#define CAP   256
typedef unsigned long long u64;

#define FASTVAL 0.4317347049363836f   // -ln(1e-6)/32

// ---- packed f32x2 helpers (sm_100+) ----
__device__ __forceinline__ u64 pk2(float lo, float hi) {
    u64 r; asm("mov.b64 %0, {%1, %2};" : "=l"(r) : "f"(lo), "f"(hi)); return r;
}
__device__ __forceinline__ float2 up2(u64 v) {
    float2 f; asm("mov.b64 {%0, %1}, %2;" : "=f"(f.x), "=f"(f.y) : "l"(v)); return f;
}
__device__ __forceinline__ u64 f2fma(u64 a, u64 b, u64 c) {
    u64 d; asm("fma.rn.f32x2 %0, %1, %2, %3;" : "=l"(d) : "l"(a), "l"(b), "l"(c)); return d;
}
__device__ __forceinline__ u64 f2mul(u64 a, u64 b) {
    u64 d; asm("mul.rn.f32x2 %0, %1, %2;" : "=l"(d) : "l"(a), "l"(b)); return d;
}
__device__ __forceinline__ u64 f2add(u64 a, u64 b) {
    u64 d; asm("add.rn.f32x2 %0, %1, %2;" : "=l"(d) : "l"(a), "l"(b)); return d;
}
__device__ __forceinline__ float sqrt_ap(float x) {
    float r; asm("sqrt.approx.f32 %0, %1;" : "=f"(r) : "f"(x)); return r;
}
__device__ __forceinline__ float ex2_ap(float x) {
    float r; asm("ex2.approx.f32 %0, %1;" : "=f"(r) : "f"(x)); return r;
}
__device__ __forceinline__ float lg2_ap(float x) {
    float r; asm("lg2.approx.f32 %0, %1;" : "=f"(r) : "f"(x)); return r;
}

__global__ void __launch_bounds__(256, 5) smoothed_fused(
    const float* __restrict__ p,
    const float* __restrict__ centers,
    const float* __restrict__ radii,
    const float* __restrict__ tfs,
    float* __restrict__ out, int npts) {

    __shared__ __align__(16) float  shc[N_SPH * 28];   // general consts
    __shared__ __align__(16) float  shc2[N_SPH * 8];   // identity consts
    __shared__ __align__(16) float4 sbuf[CAP];
    __shared__ float  spart[4 * 257];
    __shared__ float  s_red[4 * 10];                   // 4 warps x (8 oct + sum + sig)
    __shared__ __align__(16) float s_R2o[8];           // per-octant thresholds
    __shared__ int    s_count;
    __shared__ int    s_ident;

    const int tid = threadIdx.x;
    if (tid == 0) { s_count = 0; s_ident = 1; }

    // ---- prefetch this thread's 4 points ----
    int t = blockIdx.x * 256 + tid;
    int base = t * 4;
    float4 va, vb, vc;
    bool inb = base < npts;
    if (inb) {
        const float4* p4 = reinterpret_cast<const float4*>(p);
        int f = t * 3;
        va = p4[f]; vb = p4[f + 1]; vc = p4[f + 2];
    }
    __syncthreads();   // init visible

    // ---- phase A: consts + directional LSE threshold terms ----
    float my_sum = 0.0f, my_sig = 1e30f;
    float my_oct[8];
    #pragma unroll
    for (int o = 0; o < 8; ++o) my_oct[o] = 0.0f;

    if (tid < N_SPH) {
        int i = tid;
        float T[3][3];
        bool identl = true;
        #pragma unroll
        for (int r = 0; r < 3; ++r)
            #pragma unroll
            for (int c = 0; c < 3; ++c) {
                float tv = tfs[i * 9 + r * 3 + c];
                if (tv != 0.0f) identl = false;
                T[r][c] = tv + ((r == c) ? 1.0f : 0.0f);
            }
        if (!identl) atomicAnd(&s_ident, 0);

        float cx = centers[i * 3], cy = centers[i * 3 + 1], cz = centers[i * 3 + 2];
        float rad = radii[i];
        float b = 46.16624130844683f * rad;  // 32*log2(e)*r

        float* s = shc + i * 28;
        #pragma unroll
        for (int r = 0; r < 3; ++r) {
            float cs3[4] = {T[r][0], T[r][1], T[r][2],
                            (r == 0 ? -cx : (r == 1 ? -cy : -cz))};
            #pragma unroll
            for (int c = 0; c < 4; ++c) {
                s[(r * 4 + c) * 2]     = cs3[c];
                s[(r * 4 + c) * 2 + 1] = cs3[c];
            }
        }
        s[24] = b; s[25] = b; s[26] = 0.f; s[27] = 0.f;

        float* s2 = shc2 + i * 8;
        s2[0] = -cx; s2[1] = -cx;
        s2[2] = -cy; s2[3] = -cy;
        s2[4] = -cz; s2[5] = -cz;
        s2[6] = b;   s2[7] = b;

        // sigma_min lower bound
        float M00 = 0, M11 = 0, M22 = 0, M01 = 0, M02 = 0, M12 = 0;
        #pragma unroll
        for (int k = 0; k < 3; ++k) {
            float t0 = T[k][0], t1 = T[k][1], t2 = T[k][2];
            M00 = fmaf(t0, t0, M00); M11 = fmaf(t1, t1, M11); M22 = fmaf(t2, t2, M22);
            M01 = fmaf(t0, t1, M01); M02 = fmaf(t0, t2, M02); M12 = fmaf(t1, t2, M12);
        }
        float q  = (M00 + M11 + M22) * (1.0f / 3.0f);
        float a0 = M00 - q, a1 = M11 - q, a2 = M22 - q;
        float p2 = a0 * a0 + a1 * a1 + a2 * a2
                 + 2.0f * (M01 * M01 + M02 * M02 + M12 * M12);
        float lmin = q - 2.001f * sqrtf(fmaxf(p2, 0.0f) * (1.0f / 6.0f)) - 1e-6f;
        my_sig = sqrtf(fmaxf(lmin, 0.0f)) * 0.999f;

        // global LSE term (fallback, any T)
        float cn = sqrtf(cx * cx + cy * cy + cz * cz) * 1.0002f + 1e-7f;
        my_sum = expf(32.0f * (cn + rad));

        // per-octant directional terms (valid for identity T only):
        // c . p_hat <= ||c+_o||, c+_o,k = max(sign_k * c_k, 0)
        float cxp = fmaxf(cx, 0.f), cxn = fmaxf(-cx, 0.f);
        float cyp = fmaxf(cy, 0.f), cyn = fmaxf(-cy, 0.f);
        float czp = fmaxf(cz, 0.f), czn = fmaxf(-cz, 0.f);
        #pragma unroll
        for (int o = 0; o < 8; ++o) {
            float ox = (o & 1) ? cxn : cxp;
            float oy = (o & 2) ? cyn : cyp;
            float oz = (o & 4) ? czn : czp;
            float cno = sqrtf(ox * ox + oy * oy + oz * oz) * 1.0002f + 1e-7f;
            my_oct[o] = expf(32.0f * (cno + rad));
        }
    }
    // butterfly reduce 10 values across each warp
    #pragma unroll
    for (int d = 16; d; d >>= 1) {
        my_sum += __shfl_xor_sync(0xffffffffu, my_sum, d);
        my_sig  = fminf(my_sig, __shfl_xor_sync(0xffffffffu, my_sig, d));
        #pragma unroll
        for (int o = 0; o < 8; ++o)
            my_oct[o] += __shfl_xor_sync(0xffffffffu, my_oct[o], d);
    }
    if ((tid & 31) == 0 && tid < N_SPH) {
        int w = tid >> 5;
        s_red[w * 10 + 0] = my_sum;
        s_red[w * 10 + 1] = my_sig;
        #pragma unroll
        for (int o = 0; o < 8; ++o) s_red[w * 10 + 2 + o] = my_oct[o];
    }
    __syncthreads();
    if (tid == 0) {
        float sigg = fminf(fminf(s_red[1], s_red[11]), fminf(s_red[21], s_red[31]));
        bool id = (s_ident != 0);
        #pragma unroll
        for (int o = 0; o < 8; ++o) {
            float S;
            if (id) S = ((s_red[2 + o] + s_red[12 + o]) +
                         (s_red[22 + o] + s_red[32 + o])) * 1.01f;
            else    S = ((s_red[0] + s_red[10]) + (s_red[20] + s_red[30])) * 1.01f;
            float thr2 = 1e30f;
            if (sigg > 1e-6f && !(S != S)) {
                float Rnum = logf(S) + 13.8155106f + 0.03f;
                if (Rnum <= 0.0f)      thr2 = 0.0f;
                else if (Rnum < 1e15f) { float R = Rnum / (32.0f * sigg); thr2 = R * R * 1.002f; }
            }
            s_R2o[o] = thr2;
        }
    }
    __syncthreads();
    int ident = s_ident;
    // load octant thresholds into named registers (SEL-tree select, no spills)
    float4 tA = *reinterpret_cast<const float4*>(&s_R2o[0]);
    float4 tB = *reinterpret_cast<const float4*>(&s_R2o[4]);

    // ---- phase B: classify, compact ----
    float x[4], y[4], z[4];
    bool nearf[4] = {false, false, false, false};
    int cnt = 0;
    if (inb) {
        x[0] = va.x; y[0] = va.y; z[0] = va.z;
        x[1] = va.w; y[1] = vb.x; z[1] = vb.y;
        x[2] = vb.z; y[2] = vb.w; z[2] = vc.x;
        x[3] = vc.y; y[3] = vc.z; z[3] = vc.w;
        #pragma unroll
        for (int k = 0; k < 4; ++k) {
            // octant threshold via nested selects
            float rz0 = (y[k] < 0.f) ? ((x[k] < 0.f) ? tA.w : tA.z)
                                     : ((x[k] < 0.f) ? tA.y : tA.x);
            float rz1 = (y[k] < 0.f) ? ((x[k] < 0.f) ? tB.w : tB.z)
                                     : ((x[k] < 0.f) ? tB.y : tB.x);
            float R2  = (z[k] < 0.f) ? rz1 : rz0;
            float n2 = fmaf(x[k], x[k], fmaf(y[k], y[k], z[k] * z[k]));
            nearf[k] = n2 < R2;
            cnt += nearf[k] ? 1 : 0;
        }
        if (cnt == 0) {
            *reinterpret_cast<float4*>(out + base) =
                make_float4(FASTVAL, FASTVAL, FASTVAL, FASTVAL);
        } else {
            #pragma unroll
            for (int k = 0; k < 4; ++k)
                if (!nearf[k]) out[base + k] = FASTVAL;
        }
    }
    unsigned mask = 0xffffffffu;
    int lane = tid & 31;
    int incl = cnt;
    #pragma unroll
    for (int d = 1; d < 32; d <<= 1) {
        int v = __shfl_up_sync(mask, incl, d);
        if (lane >= d) incl += v;
    }
    int total = __shfl_sync(mask, incl, 31);
    int wbase = 0;
    if (lane == 0) wbase = (total > 0) ? atomicAdd(&s_count, total) : 0;
    wbase = __shfl_sync(mask, wbase, 0);
    int off = wbase + incl - cnt;
    #pragma unroll
    for (int k = 0; k < 4; ++k) {
        if (nearf[k]) {
            if (off < CAP) {
                sbuf[off] = make_float4(x[k], y[k], z[k], __int_as_float(base + k));
            } else {
                // overflow slow path: full scalar loop (correct, rare)
                float ssum = 0.f;
                for (int i = 0; i < N_SPH; ++i) {
                    const float* s = shc + i * 28;
                    float qx = fmaf(s[0], x[k], fmaf(s[2],  y[k], fmaf(s[4],  z[k], s[6])));
                    float qy = fmaf(s[8], x[k], fmaf(s[10], y[k], fmaf(s[12], z[k], s[14])));
                    float qz = fmaf(s[16], x[k], fmaf(s[18], y[k], fmaf(s[20], z[k], s[22])));
                    float d2 = fmaf(qx, qx, fmaf(qy, qy, qz * qz));
                    ssum += ex2_ap(fmaf(sqrt_ap(d2), -46.16624130844683f, s[24]));
                }
                out[base + k] = lg2_ap(fmaxf(ssum, 1e-6f)) * -0.021660849392498290f;
            }
            off++;
        }
    }
    __syncthreads();

    // ---- phase C: unit = (pair j, group g of 32 spheres); warp-uniform g ----
    int count = min(s_count, CAP);
    int pairs = (count + 1) >> 1;
    int total_u = ((pairs + 31) >> 5) << 7;   // pairs rounded to 32, x4 groups

    for (int u = tid; u < total_u; u += 256) {
        int j = ((u >> 7) << 5) | (u & 31);
        int g = (u >> 5) & 3;
        if (j >= pairs) continue;

        int ia = 2 * j;
        int ib = min(2 * j + 1, count - 1);
        float4 A = sbuf[ia];
        float4 B = sbuf[ib];

        u64 X = pk2(A.x, B.x), Y = pk2(A.y, B.y), Z = pk2(A.z, B.z);
        float s0 = 0.f, s1 = 0.f;

        if (ident) {
            const float* cb2 = shc2 + g * (32 * 8);
            #pragma unroll 4
            for (int sp = 0; sp < 32; ++sp) {
                const ulonglong2* C = reinterpret_cast<const ulonglong2*>(cb2 + sp * 8);
                ulonglong2 n0 = C[0];  // (ncx, ncy)
                ulonglong2 n1 = C[1];  // (ncz, b)
                u64 qx = f2add(X, n0.x);
                u64 qy = f2add(Y, n0.y);
                u64 qz = f2add(Z, n1.x);
                u64 d2 = f2fma(qx, qx, f2fma(qy, qy, f2mul(qz, qz)));
                float2 d  = up2(d2);
                float2 bs = up2(n1.y);
                s0 += ex2_ap(fmaf(sqrt_ap(d.x), -46.16624130844683f, bs.x));
                s1 += ex2_ap(fmaf(sqrt_ap(d.y), -46.16624130844683f, bs.y));
            }
        } else {
            const float* cb = shc + g * (32 * 28);
            #pragma unroll 4
            for (int sp = 0; sp < 32; ++sp) {
                const ulonglong2* C = reinterpret_cast<const ulonglong2*>(cb + sp * 28);
                ulonglong2 m0 = C[0], m1 = C[1], m2 = C[2];
                ulonglong2 m3 = C[3], m4 = C[4], m5 = C[5];
                u64 bb = reinterpret_cast<const u64*>(C)[12];
                u64 qx = f2fma(m0.x, X, f2fma(m0.y, Y, f2fma(m1.x, Z, m1.y)));
                u64 qy = f2fma(m2.x, X, f2fma(m2.y, Y, f2fma(m3.x, Z, m3.y)));
                u64 qz = f2fma(m4.x, X, f2fma(m4.y, Y, f2fma(m5.x, Z, m5.y)));
                u64 d2 = f2fma(qx, qx, f2fma(qy, qy, f2mul(qz, qz)));
                float2 d  = up2(d2);
                float2 bs = up2(bb);
                s0 += ex2_ap(fmaf(sqrt_ap(d.x), -46.16624130844683f, bs.x));
                s1 += ex2_ap(fmaf(sqrt_ap(d.y), -46.16624130844683f, bs.y));
            }
        }

        spart[g * 257 + ia] = s0;
        if (2 * j + 1 < count) spart[g * 257 + ib] = s1;
    }
    __syncthreads();

    // ---- phase D: fixed-order combine of 4 group partials per point ----
    const float NEG_LN2_32 = -0.021660849392498290f;
    for (int pt = tid; pt < count; pt += 256) {
        float a0 = spart[pt];
        float a1 = spart[257 + pt];
        float a2 = spart[2 * 257 + pt];
        float a3 = spart[3 * 257 + pt];
        float s = (a0 + a1) + (a2 + a3);
        out[__float_as_int(sbuf[pt].w)] = lg2_ap(fmaxf(s, 1e-6f)) * NEG_LN2_32;
    }
}

extern "C" void kernel_launch(void* const* d_in, const int* in_sizes, int n_in,
                              void* d_out, int out_size) {
    const float* p       = (const float*)d_in[0];
    const float* centers = (const float*)d_in[1];
    const float* radii   = (const float*)d_in[2];
    const float* tfs     = (const float*)d_in[3];
    float* out = (float*)d_out;

    int npts = in_sizes[0] / 3;
    int blocks = (npts + 1023) / 1024;  // 256 threads x 4 points
    smoothed_fused<<<blocks, 256>>>(p, centers, radii, tfs, out, npts);
}

// round 16
// speedup vs baseline: 1.1082x; 1.0960x over previous
#include <cuda_runtime.h>

#define N_SPH 128
#define CAP   256
typedef unsigned long long u64;

#define FASTVAL 0.4317347049363836f   // -ln(1e-6)/32

// ---- packed f32x2 helpers (sm_100+) ----
__device__ __forceinline__ u64 pk2(float lo, float hi) {
    u64 r; asm("mov.b64 %0, {%1, %2};" : "=l"(r) : "f"(lo), "f"(hi)); return r;
}
__device__ __forceinline__ float2 up2(u64 v) {
    float2 f; asm("mov.b64 {%0, %1}, %2;" : "=f"(f.x), "=f"(f.y) : "l"(v)); return f;
}
__device__ __forceinline__ u64 f2fma(u64 a, u64 b, u64 c) {
    u64 d; asm("fma.rn.f32x2 %0, %1, %2, %3;" : "=l"(d) : "l"(a), "l"(b), "l"(c)); return d;
}
__device__ __forceinline__ u64 f2mul(u64 a, u64 b) {
    u64 d; asm("mul.rn.f32x2 %0, %1, %2;" : "=l"(d) : "l"(a), "l"(b)); return d;
}
__device__ __forceinline__ u64 f2add(u64 a, u64 b) {
    u64 d; asm("add.rn.f32x2 %0, %1, %2;" : "=l"(d) : "l"(a), "l"(b)); return d;
}
__device__ __forceinline__ float sqrt_ap(float x) {
    float r; asm("sqrt.approx.f32 %0, %1;" : "=f"(r) : "f"(x)); return r;
}
__device__ __forceinline__ float ex2_ap(float x) {
    float r; asm("ex2.approx.f32 %0, %1;" : "=f"(r) : "f"(x)); return r;
}
__device__ __forceinline__ float lg2_ap(float x) {
    float r; asm("lg2.approx.f32 %0, %1;" : "=f"(r) : "f"(x)); return r;
}

__global__ void __launch_bounds__(256, 5) smoothed_fused(
    const float* __restrict__ p,
    const float* __restrict__ centers,
    const float* __restrict__ radii,
    const float* __restrict__ tfs,
    float* __restrict__ out, int npts) {

    __shared__ __align__(16) float  shc[N_SPH * 28];   // general consts (built iff !ident)
    __shared__ __align__(16) float  shc2[N_SPH * 8];   // identity consts
    __shared__ __align__(16) float4 sbuf[CAP];
    __shared__ float  spart[4 * 257];
    __shared__ float  s_red[8];
    __shared__ float  s_R2;
    __shared__ int    s_count;
    __shared__ int    s_ident;

    const int tid = threadIdx.x;
    if (tid == 0) { s_count = 0; s_ident = 1; }

    // ---- prefetch this thread's 4 points ----
    int t = blockIdx.x * 256 + tid;
    int base = t * 4;
    float4 va, vb, vc;
    bool inb = base < npts;
    if (inb) {
        const float4* p4 = reinterpret_cast<const float4*>(p);
        int f = t * 3;
        va = p4[f]; vb = p4[f + 1]; vc = p4[f + 2];
    }
    __syncthreads();   // s_count / s_ident init visible

    // ---- phase A: threads 0..127 detect identity, build identity consts,
    //      compute LSE threshold terms; general consts deferred ----
    float my_sum = 0.0f, my_sig = 1e30f;
    float T00, T01, T02, T10, T11, T12, T20, T21, T22;
    float cx = 0.f, cy = 0.f, cz = 0.f, rad = 0.f, bcoef = 0.f;
    if (tid < N_SPH) {
        int i = tid;
        bool identl = true;
        float Tv[9];
        #pragma unroll
        for (int k = 0; k < 9; ++k) {
            float tv = tfs[i * 9 + k];
            if (tv != 0.0f) identl = false;
            Tv[k] = tv;
        }
        T00 = Tv[0] + 1.0f; T01 = Tv[1];        T02 = Tv[2];
        T10 = Tv[3];        T11 = Tv[4] + 1.0f; T12 = Tv[5];
        T20 = Tv[6];        T21 = Tv[7];        T22 = Tv[8] + 1.0f;
        if (!identl) atomicAnd(&s_ident, 0);

        cx = centers[i * 3]; cy = centers[i * 3 + 1]; cz = centers[i * 3 + 2];
        rad = radii[i];
        bcoef = 46.16624130844683f * rad;  // 32*log2(e)*r

        float* s2 = shc2 + i * 8;
        s2[0] = -cx; s2[1] = -cx;
        s2[2] = -cy; s2[3] = -cy;
        s2[4] = -cz; s2[5] = -cz;
        s2[6] = bcoef; s2[7] = bcoef;

        // sigma_min lower bound: lambda_min(T^T T) >= q - 2*sqrt(p2/6)
        float M00 = 0, M11 = 0, M22 = 0, M01 = 0, M02 = 0, M12 = 0;
        {
            float r0x = T00, r0y = T01, r0z = T02;
            float r1x = T10, r1y = T11, r1z = T12;
            float r2x = T20, r2y = T21, r2z = T22;
            M00 = r0x*r0x + r1x*r1x + r2x*r2x;
            M11 = r0y*r0y + r1y*r1y + r2y*r2y;
            M22 = r0z*r0z + r1z*r1z + r2z*r2z;
            M01 = r0x*r0y + r1x*r1y + r2x*r2y;
            M02 = r0x*r0z + r1x*r1z + r2x*r2z;
            M12 = r0y*r0z + r1y*r1z + r2y*r2z;
        }
        float q  = (M00 + M11 + M22) * (1.0f / 3.0f);
        float a0 = M00 - q, a1 = M11 - q, a2 = M22 - q;
        float p2 = a0 * a0 + a1 * a1 + a2 * a2
                 + 2.0f * (M01 * M01 + M02 * M02 + M12 * M12);
        float lmin = q - 2.001f * sqrtf(fmaxf(p2, 0.0f) * (1.0f / 6.0f)) - 1e-6f;
        my_sig = sqrtf(fmaxf(lmin, 0.0f)) * 0.999f;

        // LSE term: a_i = ||c_i|| + r_i (upper bound, inflated)
        float cn = sqrtf(cx * cx + cy * cy + cz * cz) * 1.0002f + 1e-7f;
        my_sum = expf(32.0f * (cn + rad));
    }
    // warp butterfly reduce (deterministic), 4 warps carry data
    #pragma unroll
    for (int d = 16; d; d >>= 1) {
        my_sum += __shfl_xor_sync(0xffffffffu, my_sum, d);
        my_sig  = fminf(my_sig, __shfl_xor_sync(0xffffffffu, my_sig, d));
    }
    if ((tid & 31) == 0 && tid < N_SPH) {
        s_red[tid >> 5]       = my_sum;
        s_red[(tid >> 5) + 4] = my_sig;
    }
    __syncthreads();   // s_ident final, s_red ready

    // build general consts only if some transform is non-identity
    if (!s_ident && tid < N_SPH) {
        float* s = shc + tid * 28;
        float row[12] = {T00, T01, T02, -cx, T10, T11, T12, -cy, T20, T21, T22, -cz};
        #pragma unroll
        for (int k = 0; k < 12; ++k) { s[2 * k] = row[k]; s[2 * k + 1] = row[k]; }
        s[24] = bcoef; s[25] = bcoef; s[26] = 0.f; s[27] = 0.f;
    }
    if (tid == 0) {
        float S    = ((s_red[0] + s_red[1]) + (s_red[2] + s_red[3])) * 1.01f;
        float sigg = fminf(fminf(s_red[4], s_red[5]), fminf(s_red[6], s_red[7]));
        float thr2 = 1e30f;                          // default: no culling
        if (sigg > 1e-6f && !(S != S)) {             // S NaN-guard
            float Rnum = logf(S) + 13.8155106f + 0.03f;   // ln S + ln 1e6 + delta
            if (Rnum <= 0.0f)      thr2 = 0.0f;      // everything clamps
            else if (Rnum < 1e15f) { float R = Rnum / (32.0f * sigg); thr2 = R * R * 1.002f; }
        }
        s_R2 = thr2;
    }
    __syncthreads();   // shc (if built) + s_R2 visible
    float R2 = s_R2;
    int ident = s_ident;

    // ---- phase B: classify, compact into shared (cap CAP), overflow slow path ----
    float x[4], y[4], z[4];
    bool nearf[4] = {false, false, false, false};
    int cnt = 0;
    if (inb) {
        x[0] = va.x; y[0] = va.y; z[0] = va.z;
        x[1] = va.w; y[1] = vb.x; z[1] = vb.y;
        x[2] = vb.z; y[2] = vb.w; z[2] = vc.x;
        x[3] = vc.y; y[3] = vc.z; z[3] = vc.w;
        #pragma unroll
        for (int k = 0; k < 4; ++k) {
            float n2 = fmaf(x[k], x[k], fmaf(y[k], y[k], z[k] * z[k]));
            nearf[k] = n2 < R2;
            cnt += nearf[k] ? 1 : 0;
        }
        if (cnt == 0) {
            // all 4 far: one vector store on the dominant path
            *reinterpret_cast<float4*>(out + base) =
                make_float4(FASTVAL, FASTVAL, FASTVAL, FASTVAL);
        } else {
            #pragma unroll
            for (int k = 0; k < 4; ++k)
                if (!nearf[k]) out[base + k] = FASTVAL;
        }
    }
    unsigned mask = 0xffffffffu;
    int lane = tid & 31;
    int incl = cnt;
    #pragma unroll
    for (int d = 1; d < 32; d <<= 1) {
        int v = __shfl_up_sync(mask, incl, d);
        if (lane >= d) incl += v;
    }
    int total = __shfl_sync(mask, incl, 31);
    int wbase = 0;
    if (lane == 0) wbase = (total > 0) ? atomicAdd(&s_count, total) : 0;
    wbase = __shfl_sync(mask, wbase, 0);
    int off = wbase + incl - cnt;
    #pragma unroll
    for (int k = 0; k < 4; ++k) {
        if (nearf[k]) {
            if (off < CAP) {
                sbuf[off] = make_float4(x[k], y[k], z[k], __int_as_float(base + k));
            } else {
                // overflow slow path: full scalar loop (correct, rare)
                float ssum = 0.f;
                if (ident) {
                    for (int i = 0; i < N_SPH; ++i) {
                        const float* s2 = shc2 + i * 8;
                        float qx = x[k] + s2[0];
                        float qy = y[k] + s2[2];
                        float qz = z[k] + s2[4];
                        float d2 = fmaf(qx, qx, fmaf(qy, qy, qz * qz));
                        ssum += ex2_ap(fmaf(sqrt_ap(d2), -46.16624130844683f, s2[6]));
                    }
                } else {
                    for (int i = 0; i < N_SPH; ++i) {
                        const float* s = shc + i * 28;
                        float qx = fmaf(s[0], x[k], fmaf(s[2],  y[k], fmaf(s[4],  z[k], s[6])));
                        float qy = fmaf(s[8], x[k], fmaf(s[10], y[k], fmaf(s[12], z[k], s[14])));
                        float qz = fmaf(s[16], x[k], fmaf(s[18], y[k], fmaf(s[20], z[k], s[22])));
                        float d2 = fmaf(qx, qx, fmaf(qy, qy, qz * qz));
                        ssum += ex2_ap(fmaf(sqrt_ap(d2), -46.16624130844683f, s[24]));
                    }
                }
                out[base + k] = lg2_ap(fmaxf(ssum, 1e-6f)) * -0.021660849392498290f;
            }
            off++;
        }
    }
    __syncthreads();

    // ---- phase C: unit = (pair j, group g of 32 spheres); warp-uniform g ----
    int count = min(s_count, CAP);
    int pairs = (count + 1) >> 1;
    int total_u = ((pairs + 31) >> 5) << 7;   // pairs rounded to 32, x4 groups

    for (int u = tid; u < total_u; u += 256) {
        int j = ((u >> 7) << 5) | (u & 31);
        int g = (u >> 5) & 3;
        if (j >= pairs) continue;

        int ia = 2 * j;
        int ib = min(2 * j + 1, count - 1);
        float4 A = sbuf[ia];
        float4 B = sbuf[ib];

        u64 X = pk2(A.x, B.x), Y = pk2(A.y, B.y), Z = pk2(A.z, B.z);
        float s0 = 0.f, s1 = 0.f;

        if (ident) {
            const float* cb2 = shc2 + g * (32 * 8);
            #pragma unroll 4
            for (int sp = 0; sp < 32; ++sp) {
                const ulonglong2* C = reinterpret_cast<const ulonglong2*>(cb2 + sp * 8);
                ulonglong2 n0 = C[0];  // (ncx, ncy)
                ulonglong2 n1 = C[1];  // (ncz, b)
                u64 qx = f2add(X, n0.x);
                u64 qy = f2add(Y, n0.y);
                u64 qz = f2add(Z, n1.x);
                u64 d2 = f2fma(qx, qx, f2fma(qy, qy, f2mul(qz, qz)));
                float2 d  = up2(d2);
                float2 bs = up2(n1.y);
                s0 += ex2_ap(fmaf(sqrt_ap(d.x), -46.16624130844683f, bs.x));
                s1 += ex2_ap(fmaf(sqrt_ap(d.y), -46.16624130844683f, bs.y));
            }
        } else {
            const float* cb = shc + g * (32 * 28);
            #pragma unroll 4
            for (int sp = 0; sp < 32; ++sp) {
                const ulonglong2* C = reinterpret_cast<const ulonglong2*>(cb + sp * 28);
                ulonglong2 m0 = C[0], m1 = C[1], m2 = C[2];
                ulonglong2 m3 = C[3], m4 = C[4], m5 = C[5];
                u64 bb = reinterpret_cast<const u64*>(C)[12];
                u64 qx = f2fma(m0.x, X, f2fma(m0.y, Y, f2fma(m1.x, Z, m1.y)));
                u64 qy = f2fma(m2.x, X, f2fma(m2.y, Y, f2fma(m3.x, Z, m3.y)));
                u64 qz = f2fma(m4.x, X, f2fma(m4.y, Y, f2fma(m5.x, Z, m5.y)));
                u64 d2 = f2fma(qx, qx, f2fma(qy, qy, f2mul(qz, qz)));
                float2 d  = up2(d2);
                float2 bs = up2(bb);
                s0 += ex2_ap(fmaf(sqrt_ap(d.x), -46.16624130844683f, bs.x));
                s1 += ex2_ap(fmaf(sqrt_ap(d.y), -46.16624130844683f, bs.y));
            }
        }

        spart[g * 257 + ia] = s0;
        if (2 * j + 1 < count) spart[g * 257 + ib] = s1;
    }
    __syncthreads();

    // ---- phase D: fixed-order combine of 4 group partials per point ----
    const float NEG_LN2_32 = -0.021660849392498290f;
    for (int pt = tid; pt < count; pt += 256) {
        float a0 = spart[pt];
        float a1 = spart[257 + pt];
        float a2 = spart[2 * 257 + pt];
        float a3 = spart[3 * 257 + pt];
        float s = (a0 + a1) + (a2 + a3);
        out[__float_as_int(sbuf[pt].w)] = lg2_ap(fmaxf(s, 1e-6f)) * NEG_LN2_32;
    }
}

extern "C" void kernel_launch(void* const* d_in, const int* in_sizes, int n_in,
                              void* d_out, int out_size) {
    const float* p       = (const float*)d_in[0];
    const float* centers = (const float*)d_in[1];
    const float* radii   = (const float*)d_in[2];
    const float* tfs     = (const float*)d_in[3];
    float* out = (float*)d_out;

    int npts = in_sizes[0] / 3;
    int blocks = (npts + 1023) / 1024;  // 256 threads x 4 points
    smoothed_fused<<<blocks, 256>>>(p, centers, radii, tfs, out, npts);
}

// round 17
// speedup vs baseline: 1.1342x; 1.0234x over previous
#include <cuda_runtime.h>

#define N_SPH 128
#define CAP   256
typedef unsigned long long u64;

#define FASTVAL 0.4317347049363836f   // -ln(1e-6)/32

// ---- packed f32x2 helpers (sm_100+) ----
__device__ __forceinline__ u64 pk2(float lo, float hi) {
    u64 r; asm("mov.b64 %0, {%1, %2};" : "=l"(r) : "f"(lo), "f"(hi)); return r;
}
__device__ __forceinline__ float2 up2(u64 v) {
    float2 f; asm("mov.b64 {%0, %1}, %2;" : "=f"(f.x), "=f"(f.y) : "l"(v)); return f;
}
__device__ __forceinline__ u64 f2fma(u64 a, u64 b, u64 c) {
    u64 d; asm("fma.rn.f32x2 %0, %1, %2, %3;" : "=l"(d) : "l"(a), "l"(b), "l"(c)); return d;
}
__device__ __forceinline__ u64 f2mul(u64 a, u64 b) {
    u64 d; asm("mul.rn.f32x2 %0, %1, %2;" : "=l"(d) : "l"(a), "l"(b)); return d;
}
__device__ __forceinline__ u64 f2add(u64 a, u64 b) {
    u64 d; asm("add.rn.f32x2 %0, %1, %2;" : "=l"(d) : "l"(a), "l"(b)); return d;
}
__device__ __forceinline__ float sqrt_ap(float x) {
    float r; asm("sqrt.approx.f32 %0, %1;" : "=f"(r) : "f"(x)); return r;
}
__device__ __forceinline__ float ex2_ap(float x) {
    float r; asm("ex2.approx.f32 %0, %1;" : "=f"(r) : "f"(x)); return r;
}
__device__ __forceinline__ float lg2_ap(float x) {
    float r; asm("lg2.approx.f32 %0, %1;" : "=f"(r) : "f"(x)); return r;
}

__global__ void __launch_bounds__(256, 5) smoothed_fused(
    const float* __restrict__ p,
    const float* __restrict__ centers,
    const float* __restrict__ radii,
    const float* __restrict__ tfs,
    float* __restrict__ out, int npts) {

    __shared__ __align__(16) float  shc[N_SPH * 28];   // general consts
    __shared__ __align__(16) float  shc2[N_SPH * 8];   // identity consts
    __shared__ __align__(16) float4 sbuf[CAP];
    __shared__ float  spart[4 * 257];
    __shared__ float  s_red[12];                       // 4x sum, 4x sig, 4x identmin
    __shared__ int    s_count;

    const int tid = threadIdx.x;
    if (tid == 0) s_count = 0;   // ordered by the phase-A-end barrier

    // ---- prefetch this thread's 4 points ----
    int t = blockIdx.x * 256 + tid;
    int base = t * 4;
    float4 va, vb, vc;
    bool inb = base < npts;
    if (inb) {
        const float4* p4 = reinterpret_cast<const float4*>(p);
        int f = t * 3;
        va = p4[f]; vb = p4[f + 1]; vc = p4[f + 2];
    }

    // ---- phase A: threads 0..127 build consts + LSE threshold terms ----
    float my_sum = 0.0f, my_sig = 1e30f, my_idf = 1e30f;
    if (tid < N_SPH) {
        int i = tid;
        float T[3][3];
        bool identl = true;
        #pragma unroll
        for (int r = 0; r < 3; ++r)
            #pragma unroll
            for (int c = 0; c < 3; ++c) {
                float tv = tfs[i * 9 + r * 3 + c];
                if (tv != 0.0f) identl = false;
                T[r][c] = tv + ((r == c) ? 1.0f : 0.0f);
            }
        my_idf = identl ? 1.0f : 0.0f;

        float cx = centers[i * 3], cy = centers[i * 3 + 1], cz = centers[i * 3 + 2];
        float rad = radii[i];
        float b = 46.16624130844683f * rad;  // 32*log2(e)*r

        float* s = shc + i * 28;
        #pragma unroll
        for (int r = 0; r < 3; ++r) {
            float cs3[4] = {T[r][0], T[r][1], T[r][2],
                            (r == 0 ? -cx : (r == 1 ? -cy : -cz))};
            #pragma unroll
            for (int c = 0; c < 4; ++c) {
                s[(r * 4 + c) * 2]     = cs3[c];
                s[(r * 4 + c) * 2 + 1] = cs3[c];
            }
        }
        s[24] = b; s[25] = b; s[26] = 0.f; s[27] = 0.f;

        float* s2 = shc2 + i * 8;
        s2[0] = -cx; s2[1] = -cx;
        s2[2] = -cy; s2[3] = -cy;
        s2[4] = -cz; s2[5] = -cz;
        s2[6] = b;   s2[7] = b;

        // sigma_min lower bound: lambda_min(T^T T) >= q - 2*sqrt(p2/6)
        float M00 = 0, M11 = 0, M22 = 0, M01 = 0, M02 = 0, M12 = 0;
        #pragma unroll
        for (int k = 0; k < 3; ++k) {
            float t0 = T[k][0], t1 = T[k][1], t2 = T[k][2];
            M00 = fmaf(t0, t0, M00); M11 = fmaf(t1, t1, M11); M22 = fmaf(t2, t2, M22);
            M01 = fmaf(t0, t1, M01); M02 = fmaf(t0, t2, M02); M12 = fmaf(t1, t2, M12);
        }
        float q  = (M00 + M11 + M22) * (1.0f / 3.0f);
        float a0 = M00 - q, a1 = M11 - q, a2 = M22 - q;
        float p2 = a0 * a0 + a1 * a1 + a2 * a2
                 + 2.0f * (M01 * M01 + M02 * M02 + M12 * M12);
        float lmin = q - 2.001f * sqrtf(fmaxf(p2, 0.0f) * (1.0f / 6.0f)) - 1e-6f;
        my_sig = sqrtf(fmaxf(lmin, 0.0f)) * 0.999f;   // one-sided lower bound

        // LSE term: a_i = ||c_i|| + r_i (upper bound, inflated)
        float cn = sqrtf(cx * cx + cy * cy + cz * cz) * 1.0002f + 1e-7f;
        my_sum = expf(32.0f * (cn + rad));   // inf on overflow -> no culling (safe)
    }
    // warp butterfly reduce (deterministic), 4 warps carry data
    #pragma unroll
    for (int d = 16; d; d >>= 1) {
        my_sum += __shfl_xor_sync(0xffffffffu, my_sum, d);
        my_sig  = fminf(my_sig, __shfl_xor_sync(0xffffffffu, my_sig, d));
        my_idf  = fminf(my_idf, __shfl_xor_sync(0xffffffffu, my_idf, d));
    }
    if ((tid & 31) == 0 && tid < N_SPH) {
        int w = tid >> 5;
        s_red[w]     = my_sum;
        s_red[w + 4] = my_sig;
        s_red[w + 8] = my_idf;
    }
    __syncthreads();   // s_red + shc/shc2 + s_count=0 all visible

    // every thread computes the threshold redundantly (no serial section, no barrier)
    float R2;
    int ident;
    {
        float S    = ((s_red[0] + s_red[1]) + (s_red[2] + s_red[3])) * 1.01f;
        float sigg = fminf(fminf(s_red[4], s_red[5]), fminf(s_red[6], s_red[7]));
        float idm  = fminf(fminf(s_red[8], s_red[9]), fminf(s_red[10], s_red[11]));
        ident = (idm > 0.5f) ? 1 : 0;
        float thr2 = 1e30f;                          // default: no culling
        if (sigg > 1e-6f && !(S != S)) {             // S NaN-guard
            float Rnum = logf(S) + 13.8155106f + 0.03f;   // ln S + ln 1e6 + delta
            if (Rnum <= 0.0f)      thr2 = 0.0f;      // everything clamps
            else if (Rnum < 1e15f) { float R = Rnum / (32.0f * sigg); thr2 = R * R * 1.002f; }
        }
        R2 = thr2;
    }

    // ---- phase B: classify, compact into shared (cap CAP), overflow slow path ----
    float x[4], y[4], z[4];
    bool nearf[4] = {false, false, false, false};
    int cnt = 0;
    if (inb) {
        x[0] = va.x; y[0] = va.y; z[0] = va.z;
        x[1] = va.w; y[1] = vb.x; z[1] = vb.y;
        x[2] = vb.z; y[2] = vb.w; z[2] = vc.x;
        x[3] = vc.y; y[3] = vc.z; z[3] = vc.w;
        #pragma unroll
        for (int k = 0; k < 4; ++k) {
            float n2 = fmaf(x[k], x[k], fmaf(y[k], y[k], z[k] * z[k]));
            nearf[k] = n2 < R2;
            if (!nearf[k]) out[base + k] = FASTVAL;
            cnt += nearf[k] ? 1 : 0;
        }
    }
    unsigned mask = 0xffffffffu;
    int lane = tid & 31;
    int incl = cnt;
    #pragma unroll
    for (int d = 1; d < 32; d <<= 1) {
        int v = __shfl_up_sync(mask, incl, d);
        if (lane >= d) incl += v;
    }
    int total = __shfl_sync(mask, incl, 31);
    int wbase = 0;
    if (lane == 0) wbase = (total > 0) ? atomicAdd(&s_count, total) : 0;
    wbase = __shfl_sync(mask, wbase, 0);
    int off = wbase + incl - cnt;
    #pragma unroll
    for (int k = 0; k < 4; ++k) {
        if (nearf[k]) {
            if (off < CAP) {
                sbuf[off] = make_float4(x[k], y[k], z[k], __int_as_float(base + k));
            } else {
                // overflow slow path: full scalar loop (correct, rare)
                float ssum = 0.f;
                for (int i = 0; i < N_SPH; ++i) {
                    const float* s = shc + i * 28;
                    float qx = fmaf(s[0], x[k], fmaf(s[2],  y[k], fmaf(s[4],  z[k], s[6])));
                    float qy = fmaf(s[8], x[k], fmaf(s[10], y[k], fmaf(s[12], z[k], s[14])));
                    float qz = fmaf(s[16], x[k], fmaf(s[18], y[k], fmaf(s[20], z[k], s[22])));
                    float d2 = fmaf(qx, qx, fmaf(qy, qy, qz * qz));
                    ssum += ex2_ap(fmaf(sqrt_ap(d2), -46.16624130844683f, s[24]));
                }
                out[base + k] = lg2_ap(fmaxf(ssum, 1e-6f)) * -0.021660849392498290f;
            }
            off++;
        }
    }
    __syncthreads();

    // ---- phase C: unit = (pair j, group g of 32 spheres); warp-uniform g ----
    int count = min(s_count, CAP);
    int pairs = (count + 1) >> 1;
    int total_u = ((pairs + 31) >> 5) << 7;   // pairs rounded to 32, x4 groups

    for (int u = tid; u < total_u; u += 256) {
        int j = ((u >> 7) << 5) | (u & 31);
        int g = (u >> 5) & 3;
        if (j >= pairs) continue;

        int ia = 2 * j;
        int ib = min(2 * j + 1, count - 1);
        float4 A = sbuf[ia];
        float4 B = sbuf[ib];

        u64 X = pk2(A.x, B.x), Y = pk2(A.y, B.y), Z = pk2(A.z, B.z);
        float s0 = 0.f, s1 = 0.f;

        if (ident) {
            const float* cb2 = shc2 + g * (32 * 8);
            #pragma unroll 4
            for (int sp = 0; sp < 32; ++sp) {
                const ulonglong2* C = reinterpret_cast<const ulonglong2*>(cb2 + sp * 8);
                ulonglong2 n0 = C[0];  // (ncx, ncy)
                ulonglong2 n1 = C[1];  // (ncz, b)
                u64 qx = f2add(X, n0.x);
                u64 qy = f2add(Y, n0.y);
                u64 qz = f2add(Z, n1.x);
                u64 d2 = f2fma(qx, qx, f2fma(qy, qy, f2mul(qz, qz)));
                float2 d  = up2(d2);
                float2 bs = up2(n1.y);
                s0 += ex2_ap(fmaf(sqrt_ap(d.x), -46.16624130844683f, bs.x));
                s1 += ex2_ap(fmaf(sqrt_ap(d.y), -46.16624130844683f, bs.y));
            }
        } else {
            const float* cb = shc + g * (32 * 28);
            #pragma unroll 4
            for (int sp = 0; sp < 32; ++sp) {
                const ulonglong2* C = reinterpret_cast<const ulonglong2*>(cb + sp * 28);
                ulonglong2 m0 = C[0], m1 = C[1], m2 = C[2];
                ulonglong2 m3 = C[3], m4 = C[4], m5 = C[5];
                u64 bb = reinterpret_cast<const u64*>(C)[12];
                u64 qx = f2fma(m0.x, X, f2fma(m0.y, Y, f2fma(m1.x, Z, m1.y)));
                u64 qy = f2fma(m2.x, X, f2fma(m2.y, Y, f2fma(m3.x, Z, m3.y)));
                u64 qz = f2fma(m4.x, X, f2fma(m4.y, Y, f2fma(m5.x, Z, m5.y)));
                u64 d2 = f2fma(qx, qx, f2fma(qy, qy, f2mul(qz, qz)));
                float2 d  = up2(d2);
                float2 bs = up2(bb);
                s0 += ex2_ap(fmaf(sqrt_ap(d.x), -46.16624130844683f, bs.x));
                s1 += ex2_ap(fmaf(sqrt_ap(d.y), -46.16624130844683f, bs.y));
            }
        }

        spart[g * 257 + ia] = s0;
        if (2 * j + 1 < count) spart[g * 257 + ib] = s1;
    }
    __syncthreads();

    // ---- phase D: fixed-order combine of 4 group partials per point ----
    const float NEG_LN2_32 = -0.021660849392498290f;
    for (int pt = tid; pt < count; pt += 256) {
        float a0 = spart[pt];
        float a1 = spart[257 + pt];
        float a2 = spart[2 * 257 + pt];
        float a3 = spart[3 * 257 + pt];
        float s = (a0 + a1) + (a2 + a3);
        out[__float_as_int(sbuf[pt].w)] = lg2_ap(fmaxf(s, 1e-6f)) * NEG_LN2_32;
    }
}

extern "C" void kernel_launch(void* const* d_in, const int* in_sizes, int n_in,
                              void* d_out, int out_size) {
    const float* p       = (const float*)d_in[0];
    const float* centers = (const float*)d_in[1];
    const float* radii   = (const float*)d_in[2];
    const float* tfs     = (const float*)d_in[3];
    float* out = (float*)d_out;

    int npts = in_sizes[0] / 3;
    int blocks = (npts + 1023) / 1024;  // 256 threads x 4 points
    smoothed_fused<<<blocks, 256>>>(p, centers, radii, tfs, out, npts);
}